// round 15
// baseline (speedup 1.0000x reference)
#include <cuda_runtime.h>
#include <cuda_fp16.h>
#include <cstdint>

#define B_DIM 16
#define S_DIM 2048
#define I_DIM 1024
#define H_DIM 1024
#define M_TOTAL (B_DIM * S_DIM)   // 32768

#define BM 256
#define BN 128
#define KIT 32                    // K tiles of 32 halves each
#define THREADS 256
#define STAGES 4
#define STAGE_U32 6144            // A: 256x16 u32 (16KB) + B: 128x16 u32 (8KB)
#define STAGE_BYTES 24576
#define SMEM_BYTES (STAGES * STAGE_BYTES)   // 96 KB dynamic

// Pre-permuted half buffers: row r, k-block kb (32 halves = 16 pairs),
// pair q at u32 position P(q) = 4*(q&3) + (q>>2) within the 16-u32 block.
// Lane tg LDS.128 at offset 4*tg -> pairs {tg, tg+4, tg+8, tg+12} =
// the m16n8k16 A/B fragments for both k-steps.
__device__ uint32_t g_xh[(size_t)M_TOTAL * I_DIM / 2];   // 64 MB
__device__ uint32_t g_wh[(size_t)H_DIM * I_DIM / 2];     // 2 MB
__device__ float    g_hterm[B_DIM * H_DIM];

// ---------------- helpers ----------------
__device__ __forceinline__ float tanh_fast(float v) {
    float e, r;
    asm("ex2.approx.f32 %0, %1;" : "=f"(e) : "f"(v * 2.8853900817779268f));
    asm("rcp.approx.f32 %0, %1;" : "=f"(r) : "f"(e + 1.0f));
    return fmaf(-2.0f, r, 1.0f);
}

__device__ __forceinline__ uint32_t pack_h2(float lo, float hi) {
    uint32_t r;
    asm("cvt.rn.f16x2.f32 %0, %1, %2;" : "=r"(r) : "f"(hi), "f"(lo));
    return r;
}

__device__ __forceinline__ uint32_t smem_u32(const void* p) {
    uint32_t a;
    asm("{ .reg .u64 t; cvta.to.shared.u64 t, %1; cvt.u32.u64 %0, t; }" : "=r"(a) : "l"(p));
    return a;
}

__device__ __forceinline__ void mma16816(float* d,
                                         uint32_t a0, uint32_t a1, uint32_t a2, uint32_t a3,
                                         uint32_t b0, uint32_t b1) {
    asm("mma.sync.aligned.m16n8k16.row.col.f32.f16.f16.f32 "
        "{%0,%1,%2,%3}, {%4,%5,%6,%7}, {%8,%9}, {%0,%1,%2,%3};"
        : "+f"(d[0]), "+f"(d[1]), "+f"(d[2]), "+f"(d[3])
        : "r"(a0), "r"(a1), "r"(a2), "r"(a3), "r"(b0), "r"(b1));
}

#define CP16(dst, src) \
    asm volatile("cp.async.cg.shared.global [%0], [%1], 16;" :: "r"(dst), "l"(src) : "memory")
#define CP_COMMIT() asm volatile("cp.async.commit_group;" ::: "memory")
#define CP_WAIT2()  asm volatile("cp.async.wait_group 2;" ::: "memory")

// ---------------- prepass: fp32 -> permuted fp16 (R9 version, proven) --------
__global__ __launch_bounds__(256)
void convert_kernel(const float* __restrict__ src, uint32_t* __restrict__ dst, int nrows) {
    int idx = blockIdx.x * 256 + threadIdx.x;
    if (idx >= nrows * 256) return;
    int r  = idx >> 8;
    int c8 = idx & 255;
    int kb = c8 >> 3;
    int c  = c8 & 7;
    float4 v = *(const float4*)(src + ((size_t)r << 10) + kb * 32 + c * 4);
    uint32_t h01 = pack_h2(v.x, v.y);
    uint32_t h23 = pack_h2(v.z, v.w);
    size_t base = ((size_t)r * 32 + kb) * 16;
    int p0 = 8 * (c & 1) + (c >> 1);
    dst[base + p0]     = h01;
    dst[base + p0 + 4] = h23;
}

// ---------------- hterm = hx @ W_hh^T + b_ih + b_hh (fp32 exact) ----------------
__global__ __launch_bounds__(256)
void hterm_kernel(const float* __restrict__ hx, const float* __restrict__ Whh,
                  const float* __restrict__ bih, const float* __restrict__ bhh) {
    int gw   = (blockIdx.x * blockDim.x + threadIdx.x) >> 5;
    int lane = threadIdx.x & 31;
    if (gw >= H_DIM) return;
    int h = gw;

    float acc[B_DIM];
#pragma unroll
    for (int b = 0; b < B_DIM; ++b) acc[b] = 0.0f;

    const float4* wr = (const float4*)(Whh + (size_t)h * H_DIM);
#pragma unroll
    for (int it = 0; it < H_DIM / 128; ++it) {
        int j = lane + it * 32;
        float4 w4 = wr[j];
#pragma unroll
        for (int b = 0; b < B_DIM; ++b) {
            float4 hv = ((const float4*)(hx + (size_t)b * H_DIM))[j];
            acc[b] += w4.x * hv.x + w4.y * hv.y + w4.z * hv.z + w4.w * hv.w;
        }
    }
#pragma unroll
    for (int b = 0; b < B_DIM; ++b)
#pragma unroll
        for (int o = 16; o > 0; o >>= 1)
            acc[b] += __shfl_xor_sync(0xFFFFFFFFu, acc[b], o);

    if (lane == 0) {
        float bias = bih[h] + bhh[h];
#pragma unroll
        for (int b = 0; b < B_DIM; ++b)
            g_hterm[b * H_DIM + h] = acc[b] + bias;
    }
}

// ---------------- main GEMM + tanh ----------------
// 256 threads = 8 warps, 2(M)x... 4 warps along M? No: 4(M)x2(N) of 64x64 warp
// tiles over a 256x128 CTA tile. 1 CTA/SM (~200 regs). LDS per HMMA = 0.25
// (vs 0.375 at 32x64): crossbar demand per tile drops ~35%, and each B-load
// is covered by 8 HMMA (64 tensor-cycles) of shadow.
__global__ __launch_bounds__(THREADS)
void gemm_tanh_kernel(float* __restrict__ out) {
    extern __shared__ __align__(16) uint32_t sbuf[];   // 96 KB, 4 stages

    int tid  = threadIdx.x;
    int wid  = tid >> 5;
    int lane = tid & 31;
    int g    = lane >> 2;
    int tg   = lane & 3;

    int mb = blockIdx.x >> 3;
    int nb = blockIdx.x & 7;           // 8 consecutive CTAs share x M-tile in L2
    int m0 = mb * BM;
    int n0 = nb * BN;
    int bb = m0 >> 11;

    int warp_m = (wid & 3) * 64;       // 4 warps along M (256 rows)
    int warp_n = (wid >> 2) * 64;      // 2 warps along N (128 cols)

    uint32_t sb = smem_u32(sbuf);

    // producer duty: per thread per tile, 4 A-chunks + 2 B-chunks of 16B
    int cr  = tid >> 2;                // 0..63
    int cch = (tid & 3) * 4;           // u32 chunk in 16-u32 row
    const uint32_t* srcA0 = g_xh + (size_t)(m0 + cr) * 512 + cch;
    const uint32_t* srcA1 = srcA0 + (size_t)64 * 512;
    const uint32_t* srcA2 = srcA0 + (size_t)128 * 512;
    const uint32_t* srcA3 = srcA0 + (size_t)192 * 512;
    const uint32_t* srcB0 = g_wh + (size_t)(n0 + cr) * 512 + cch;
    const uint32_t* srcB1 = srcB0 + (size_t)64 * 512;
    uint32_t dstA = sb + (cr * 16 + cch) * 4;        // A rows 0..63 base
    uint32_t dstB = dstA + 16384;                    // B at +16KB

    // tile t -> stage t&3 (byte offset (t&3)*24576), src offset t*16 u32
#define COPY_TILE(t_imm, soff) do {                                   \
    CP16(dstA + (soff),         srcA0 + (t_imm) * 16);                \
    CP16(dstA + (soff) + 4096,  srcA1 + (t_imm) * 16);                \
    CP16(dstA + (soff) + 8192,  srcA2 + (t_imm) * 16);                \
    CP16(dstA + (soff) + 12288, srcA3 + (t_imm) * 16);                \
    CP16(dstB + (soff),         srcB0 + (t_imm) * 16);                \
    CP16(dstB + (soff) + 4096,  srcB1 + (t_imm) * 16);                \
} while (0)

    COPY_TILE(0, 0);      CP_COMMIT();
    COPY_TILE(1, 24576);  CP_COMMIT();
    COPY_TILE(2, 49152);  CP_COMMIT();

    float acc[4][8][4];
#pragma unroll
    for (int mt = 0; mt < 4; ++mt)
#pragma unroll
        for (int nt = 0; nt < 8; ++nt)
#pragma unroll
            for (int r = 0; r < 4; ++r) acc[mt][nt][r] = 0.0f;

    for (int itb = 0; itb < KIT / 4; ++itb) {
#pragma unroll
        for (int j = 0; j < 4; ++j) {            // stage == j (compile-time)
            CP_WAIT2();
            __syncthreads();

            const uint32_t* sA = sbuf + j * STAGE_U32;
            const uint32_t* sB = sA + 4096;

            // A fragments: 4 m-tiles x (low,high) = 8 LDS.128
            uint4 aL[4], aH[4];
#pragma unroll
            for (int mt = 0; mt < 4; ++mt) {
                int R = warp_m + mt * 16 + g;
                aL[mt] = *(const uint4*)(sA + R * 16 + 4 * tg);
                aH[mt] = *(const uint4*)(sA + (R + 8) * 16 + 4 * tg);
            }

            int it = itb * 4 + j;
            if (it + 3 < KIT)
                COPY_TILE(j + 3, ((j + 3) & 3) * 24576);
            CP_COMMIT();

            // B streamed: load bv[nt+1] in the shadow of nt's 8 HMMA
            uint4 bnext = *(const uint4*)(sB + (warp_n + g) * 16 + 4 * tg);
#pragma unroll
            for (int nt = 0; nt < 8; ++nt) {
                uint4 b = bnext;
                if (nt < 7)
                    bnext = *(const uint4*)(sB + (warp_n + (nt + 1) * 8 + g) * 16 + 4 * tg);
#pragma unroll
                for (int mt = 0; mt < 4; ++mt) {
                    mma16816(acc[mt][nt], aL[mt].x, aH[mt].x, aL[mt].y, aH[mt].y,
                             b.x, b.y);
                    mma16816(acc[mt][nt], aL[mt].z, aH[mt].z, aL[mt].w, aH[mt].w,
                             b.z, b.w);
                }
            }
        }
        // advance source pointers by 4 tiles (64 u32)
        srcA0 += 64; srcA1 += 64; srcA2 += 64; srcA3 += 64;
        srcB0 += 64; srcB1 += 64;
    }

    // ---- epilogue: +hterm, tanh, store ----
    const float* ht = g_hterm + bb * H_DIM + n0;
#pragma unroll
    for (int mt = 0; mt < 4; ++mt) {
        int r0 = m0 + warp_m + mt * 16 + g;
#pragma unroll
        for (int nt = 0; nt < 8; ++nt) {
            int nloc = warp_n + nt * 8 + tg * 2;
            float h0 = __ldg(ht + nloc), h1 = __ldg(ht + nloc + 1);
            float* a = acc[mt][nt];
            float2 v0, v1;
            v0.x = tanh_fast(a[0] + h0);
            v0.y = tanh_fast(a[1] + h1);
            v1.x = tanh_fast(a[2] + h0);
            v1.y = tanh_fast(a[3] + h1);
            *(float2*)(out + (size_t)r0 * H_DIM + n0 + nloc) = v0;
            *(float2*)(out + (size_t)(r0 + 8) * H_DIM + n0 + nloc) = v1;
        }
    }
}

// ---------------- launch ----------------
extern "C" void kernel_launch(void* const* d_in, const int* in_sizes, int n_in,
                              void* d_out, int out_size) {
    const float* x   = (const float*)d_in[0];
    const float* hx  = (const float*)d_in[1];
    const float* Wih = (const float*)d_in[2];
    const float* Whh = (const float*)d_in[3];
    const float* bih = (const float*)d_in[4];
    const float* bhh = (const float*)d_in[5];
    float* out = (float*)d_out;

    uint32_t* xh;  cudaGetSymbolAddress((void**)&xh, g_xh);
    uint32_t* wh;  cudaGetSymbolAddress((void**)&wh, g_wh);

    cudaFuncSetAttribute(gemm_tanh_kernel,
                         cudaFuncAttributeMaxDynamicSharedMemorySize, SMEM_BYTES);

    convert_kernel<<<(M_TOTAL * 256) / 256, 256>>>(x,   xh, M_TOTAL);
    convert_kernel<<<(H_DIM  * 256) / 256, 256>>>(Wih, wh, H_DIM);
    hterm_kernel<<<H_DIM / 8, 256>>>(hx, Whh, bih, bhh);
    gemm_tanh_kernel<<<(M_TOTAL / BM) * (H_DIM / BN), THREADS, SMEM_BYTES>>>(out);
}

// round 16
// speedup vs baseline: 1.7696x; 1.7696x over previous
#include <cuda_runtime.h>
#include <cuda_fp16.h>
#include <cstdint>

#define B_DIM 16
#define S_DIM 2048
#define I_DIM 1024
#define H_DIM 1024
#define M_TOTAL (B_DIM * S_DIM)   // 32768

#define BM 128
#define BN 128
#define KIT 32                    // K iterations of 32 halves each
#define THREADS 256
#define STAGES 4
#define STAGE_U32 4096            // A: 2048 u32 (128x32 half) + B: 2048 u32
#define SMEM_BYTES (STAGES * STAGE_U32 * 4)   // 64 KB dynamic

// prep grid split
#define HTERM_BLOCKS 128
#define WCONV_BLOCKS (H_DIM * 1024 / 8 / 256)      // 512
#define XCONV_BLOCKS (M_TOTAL * 1024 / 8 / 256)    // 16384
#define PREP_BLOCKS (HTERM_BLOCKS + WCONV_BLOCKS + XCONV_BLOCKS)

// Pre-permuted half buffers: row r, k-block kb (32 halves = 16 pairs),
// pair q at u32 position P(q) = 4*(q&3) + (q>>2) (P is an involution).
// Lane tg LDS.128 at offset 4*tg -> pairs {tg, tg+4, tg+8, tg+12} =
// the m16n8k16 A/B fragments for both k-steps.
__device__ uint32_t g_xh[(size_t)M_TOTAL * I_DIM / 2];   // 64 MB
__device__ uint32_t g_wh[(size_t)H_DIM * I_DIM / 2];     // 2 MB
__device__ float    g_hterm[B_DIM * H_DIM];

// ---------------- helpers ----------------
__device__ __forceinline__ uint32_t smem_u32(const void* p) {
    uint32_t a;
    asm("{ .reg .u64 t; cvta.to.shared.u64 t, %1; cvt.u32.u64 %0, t; }" : "=r"(a) : "l"(p));
    return a;
}

__device__ __forceinline__ float tanh_fast(float v) {
    float e, r;
    asm("ex2.approx.f32 %0, %1;" : "=f"(e) : "f"(v * 2.8853900817779268f));
    asm("rcp.approx.f32 %0, %1;" : "=f"(r) : "f"(e + 1.0f));
    return fmaf(-2.0f, r, 1.0f);
}

__device__ __forceinline__ uint32_t pack_h2(float lo, float hi) {
    uint32_t r;
    asm("cvt.rn.f16x2.f32 %0, %1, %2;" : "=r"(r) : "f"(hi), "f"(lo));
    return r;
}

__device__ __forceinline__ void mma16816(float* d,
                                         uint32_t a0, uint32_t a1, uint32_t a2, uint32_t a3,
                                         uint32_t b0, uint32_t b1) {
    asm volatile(
        "mma.sync.aligned.m16n8k16.row.col.f32.f16.f16.f32 "
        "{%0,%1,%2,%3}, {%4,%5,%6,%7}, {%8,%9}, {%0,%1,%2,%3};"
        : "+f"(d[0]), "+f"(d[1]), "+f"(d[2]), "+f"(d[3])
        : "r"(a0), "r"(a1), "r"(a2), "r"(a3), "r"(b0), "r"(b1));
}

#define CP16(dst, src) \
    asm volatile("cp.async.cg.shared.global [%0], [%1], 16;" :: "r"(dst), "l"(src) : "memory")
#define CP_COMMIT() asm volatile("cp.async.commit_group;" ::: "memory")
#define CP_WAIT1()  asm volatile("cp.async.wait_group 1;" ::: "memory")
#define CP_WAIT2()  asm volatile("cp.async.wait_group 2;" ::: "memory")

// ---------------- convert body: 1 thread -> 1 uint4 (4 output words) ----------
// Output word p of a 16-u32 block holds pair q = P(p) = 4*(p&3)+(p>>2).
// Thread (kbi, w) writes words 4w..4w+3: word 4w+i needs pair q = 4i+w,
// i.e. float2 index 4i+w within the 16-float2 source block -> 4 strided
// float2 loads (one 32B sector per 128B line per warp instruction),
// one coalesced STG.128.
__device__ __forceinline__ void convert_blocks(const float* __restrict__ src,
                                               uint32_t* __restrict__ dst,
                                               int bc) {
    size_t n   = (size_t)bc * 256 + threadIdx.x;
    size_t kbi = n >> 2;
    int    w   = (int)(n & 3);
    const float2* s = (const float2*)src + kbi * 16 + w;
    uint32_t o[4];
#pragma unroll
    for (int i = 0; i < 4; ++i) {
        float2 f = s[4 * i];
        o[i] = pack_h2(f.x, f.y);
    }
    ((uint4*)dst)[kbi * 4 + w] = make_uint4(o[0], o[1], o[2], o[3]);
}

// ---------------- fused prep: hterm + convert W + convert x ------------------
__global__ __launch_bounds__(256)
void prep_kernel(const float* __restrict__ x,
                 const float* __restrict__ hx,
                 const float* __restrict__ Wih,
                 const float* __restrict__ Whh,
                 const float* __restrict__ bih,
                 const float* __restrict__ bhh) {
    int b = blockIdx.x;
    if (b < HTERM_BLOCKS) {
        // hterm = hx @ W_hh^T + b_ih + b_hh (fp32 exact); one warp per h
        int wid  = threadIdx.x >> 5;
        int lane = threadIdx.x & 31;
        int h = b * 8 + wid;

        float acc[B_DIM];
#pragma unroll
        for (int bb = 0; bb < B_DIM; ++bb) acc[bb] = 0.0f;

        const float4* wr = (const float4*)(Whh + (size_t)h * H_DIM);
#pragma unroll
        for (int it = 0; it < H_DIM / 128; ++it) {
            int j = lane + it * 32;
            float4 w4 = wr[j];
#pragma unroll
            for (int bb = 0; bb < B_DIM; ++bb) {
                float4 hv = ((const float4*)(hx + (size_t)bb * H_DIM))[j];
                acc[bb] += w4.x * hv.x + w4.y * hv.y + w4.z * hv.z + w4.w * hv.w;
            }
        }
#pragma unroll
        for (int bb = 0; bb < B_DIM; ++bb)
#pragma unroll
            for (int o = 16; o > 0; o >>= 1)
                acc[bb] += __shfl_xor_sync(0xFFFFFFFFu, acc[bb], o);

        if (lane == 0) {
            float bias = bih[h] + bhh[h];
#pragma unroll
            for (int bb = 0; bb < B_DIM; ++bb)
                g_hterm[bb * H_DIM + h] = acc[bb] + bias;
        }
    } else if (b < HTERM_BLOCKS + WCONV_BLOCKS) {
        convert_blocks(Wih, g_wh, b - HTERM_BLOCKS);
    } else {
        convert_blocks(x, g_xh, b - HTERM_BLOCKS - WCONV_BLOCKS);
    }
}

// ---------------- main GEMM + tanh (R9, best proven) ----------------
// 256 threads, 8 warps in 4(M)x2(N) grid, warp tile 32x64.
// A frags preloaded one body ahead (stage j+1 complete under wait_group 1),
// B frags streamed through a 1-deep double buffer.
__global__ __launch_bounds__(THREADS, 2)
void gemm_tanh_kernel(float* __restrict__ out) {
    extern __shared__ __align__(16) uint32_t sbuf[];   // 64 KB, 4 stages

    int tid  = threadIdx.x;
    int wid  = tid >> 5;
    int lane = tid & 31;
    int g    = lane >> 2;
    int tg   = lane & 3;

    int mb = blockIdx.x >> 3;
    int nb = blockIdx.x & 7;           // 8 consecutive CTAs share x M-tile in L2
    int m0 = mb * BM;
    int n0 = nb * BN;
    int bb = m0 >> 11;

    int warp_m = (wid & 3) * 32;
    int warp_n = (wid >> 2) * 64;

    uint32_t sb = smem_u32(sbuf);

    // producer: each thread copies 4x16B per tile (A rows cr, cr+64; B rows cr, cr+64)
    int cr  = tid >> 2;
    int cch = (tid & 3) * 4;
    const uint32_t* srcA0 = g_xh + (size_t)(m0 + cr) * 512 + cch;   // row stride 512 u32
    const uint32_t* srcA1 = srcA0 + (size_t)64 * 512;
    const uint32_t* srcB0 = g_wh + (size_t)(n0 + cr) * 512 + cch;
    const uint32_t* srcB1 = srcB0 + (size_t)64 * 512;
    uint32_t dstA0 = sb + (cr * 16 + cch) * 4;
    uint32_t dstA1 = dstA0 + 64 * 64;
    uint32_t dstB0 = dstA0 + 8192;
    uint32_t dstB1 = dstB0 + 64 * 64;

    // tile t -> stage t&3 (smem byte offset (t&3)*16384), src offset t*16 u32
#define COPY_TILE(t_imm, soff) do {                                   \
    CP16(dstA0 + (soff), srcA0 + (t_imm) * 16);                       \
    CP16(dstA1 + (soff), srcA1 + (t_imm) * 16);                       \
    CP16(dstB0 + (soff), srcB0 + (t_imm) * 16);                       \
    CP16(dstB1 + (soff), srcB1 + (t_imm) * 16);                       \
} while (0)

    COPY_TILE(0, 0);      CP_COMMIT();
    COPY_TILE(1, 16384);  CP_COMMIT();
    COPY_TILE(2, 32768);  CP_COMMIT();

    float acc[2][8][4];
#pragma unroll
    for (int mt = 0; mt < 2; ++mt)
#pragma unroll
        for (int nt = 0; nt < 8; ++nt)
#pragma unroll
            for (int r = 0; r < 4; ++r) acc[mt][nt][r] = 0.0f;

    // ---- prologue: preload body-0 fragments from stage 0 ----
    CP_WAIT2();            // group 0 complete
    __syncthreads();       // visibility of all threads' copies for stage 0

    uint4 aL0, aH0, aL1, aH1, bfrag;
    {
        const uint32_t* sA = sbuf;
        const uint32_t* sB = sbuf + 2048;
        int R = warp_m + g;
        aL0 = *(const uint4*)(sA + R * 16 + 4 * tg);
        aH0 = *(const uint4*)(sA + (R + 8) * 16 + 4 * tg);
        aL1 = *(const uint4*)(sA + (R + 16) * 16 + 4 * tg);
        aH1 = *(const uint4*)(sA + (R + 24) * 16 + 4 * tg);
        bfrag = *(const uint4*)(sB + (warp_n + g) * 16 + 4 * tg);
    }

    for (int itb = 0; itb < KIT / 4; ++itb) {
#pragma unroll
        for (int j = 0; j < 4; ++j) {            // stage == j (compile-time)
            // wait_group 1: stages j AND j+1 of this window are complete
            CP_WAIT1();
            __syncthreads();

            const uint32_t* sB  = sbuf + j * STAGE_U32 + 2048;
            const uint32_t* sAn = sbuf + ((j + 1) & 3) * STAGE_U32;
            const uint32_t* sBn = sAn + 2048;

            int it = itb * 4 + j;
            if (it + 3 < KIT)
                COPY_TILE(j + 3, ((j + 3) & 3) * 16384);
            CP_COMMIT();

            // ---- B-streamed MMA: load bV[nt+1] while computing bV[nt] ----
            uint4 bcur = bfrag;
#pragma unroll
            for (int nt = 0; nt < 8; ++nt) {
                uint4 bnxt;
                if (nt < 7)
                    bnxt = *(const uint4*)(sB + (warp_n + (nt + 1) * 8 + g) * 16 + 4 * tg);
                else
                    bnxt = *(const uint4*)(sBn + (warp_n + g) * 16 + 4 * tg); // next body nt=0
                mma16816(acc[0][nt], aL0.x, aH0.x, aL0.y, aH0.y, bcur.x, bcur.y);
                mma16816(acc[0][nt], aL0.z, aH0.z, aL0.w, aH0.w, bcur.z, bcur.w);
                mma16816(acc[1][nt], aL1.x, aH1.x, aL1.y, aH1.y, bcur.x, bcur.y);
                mma16816(acc[1][nt], aL1.z, aH1.z, aL1.w, aH1.w, bcur.z, bcur.w);
                bcur = bnxt;
            }
            bfrag = bcur;

            // ---- preload next body's A fragments (stage j+1, known complete) ----
            {
                int R = warp_m + g;
                aL0 = *(const uint4*)(sAn + R * 16 + 4 * tg);
                aH0 = *(const uint4*)(sAn + (R + 8) * 16 + 4 * tg);
                aL1 = *(const uint4*)(sAn + (R + 16) * 16 + 4 * tg);
                aH1 = *(const uint4*)(sAn + (R + 24) * 16 + 4 * tg);
            }
        }
        // advance source pointers by 4 tiles (64 u32)
        srcA0 += 64; srcA1 += 64; srcB0 += 64; srcB1 += 64;
    }

    // ---- epilogue: +hterm, tanh, store ----
    const float* ht = g_hterm + bb * H_DIM + n0;
#pragma unroll
    for (int mt = 0; mt < 2; ++mt) {
        int r0 = m0 + warp_m + mt * 16 + g;
#pragma unroll
        for (int nt = 0; nt < 8; ++nt) {
            int nloc = warp_n + nt * 8 + tg * 2;
            float h0 = __ldg(ht + nloc), h1 = __ldg(ht + nloc + 1);
            float* a = acc[mt][nt];
            float2 v0, v1;
            v0.x = tanh_fast(a[0] + h0);
            v0.y = tanh_fast(a[1] + h1);
            v1.x = tanh_fast(a[2] + h0);
            v1.y = tanh_fast(a[3] + h1);
            *(float2*)(out + (size_t)r0 * H_DIM + n0 + nloc) = v0;
            *(float2*)(out + (size_t)(r0 + 8) * H_DIM + n0 + nloc) = v1;
        }
    }
}

// ---------------- launch ----------------
extern "C" void kernel_launch(void* const* d_in, const int* in_sizes, int n_in,
                              void* d_out, int out_size) {
    const float* x   = (const float*)d_in[0];
    const float* hx  = (const float*)d_in[1];
    const float* Wih = (const float*)d_in[2];
    const float* Whh = (const float*)d_in[3];
    const float* bih = (const float*)d_in[4];
    const float* bhh = (const float*)d_in[5];
    float* out = (float*)d_out;

    cudaFuncSetAttribute(gemm_tanh_kernel,
                         cudaFuncAttributeMaxDynamicSharedMemorySize, SMEM_BYTES);

    prep_kernel<<<PREP_BLOCKS, 256>>>(x, hx, Wih, Whh, bih, bhh);
    gemm_tanh_kernel<<<(M_TOTAL / BM) * (H_DIM / BN), THREADS, SMEM_BYTES>>>(out);
}

// round 17
// speedup vs baseline: 1.7737x; 1.0023x over previous
#include <cuda_runtime.h>
#include <cuda_fp16.h>
#include <cstdint>

#define B_DIM 16
#define S_DIM 2048
#define I_DIM 1024
#define H_DIM 1024
#define M_TOTAL (B_DIM * S_DIM)   // 32768

#define BM 128
#define BN 128
#define KIT 32                    // K iterations of 32 halves each
#define THREADS 256
#define STAGES 4
#define STAGE_U32 4096            // A: 2048 u32 (128x32 half) + B: 2048 u32
#define SMEM_BYTES (STAGES * STAGE_U32 * 4)   // 64 KB dynamic

// prep grid split
#define HTERM_BLOCKS 128
#define WCONV_BLOCKS (H_DIM * 1024 / 8 / 256)      // 512
#define XCONV_BLOCKS (M_TOTAL * 1024 / 8 / 256)    // 16384
#define PREP_BLOCKS (HTERM_BLOCKS + WCONV_BLOCKS + XCONV_BLOCKS)

// Pre-permuted half buffers: row r, k-block kb (32 halves = 16 pairs),
// pair q at u32 position P(q) = 4*(q&3) + (q>>2) (P is an involution).
// Lane tg LDS.128 at offset 4*tg -> pairs {tg, tg+4, tg+8, tg+12} =
// the m16n8k16 A/B fragments for both k-steps.
__device__ uint32_t g_xh[(size_t)M_TOTAL * I_DIM / 2];   // 64 MB
__device__ uint32_t g_wh[(size_t)H_DIM * I_DIM / 2];     // 2 MB
__device__ float    g_hterm[B_DIM * H_DIM];

// ---------------- helpers ----------------
__device__ __forceinline__ uint32_t smem_u32(const void* p) {
    uint32_t a;
    asm("{ .reg .u64 t; cvta.to.shared.u64 t, %1; cvt.u32.u64 %0, t; }" : "=r"(a) : "l"(p));
    return a;
}

__device__ __forceinline__ float tanh_fast(float v) {
    float e, r;
    asm("ex2.approx.f32 %0, %1;" : "=f"(e) : "f"(v * 2.8853900817779268f));
    asm("rcp.approx.f32 %0, %1;" : "=f"(r) : "f"(e + 1.0f));
    return fmaf(-2.0f, r, 1.0f);
}

__device__ __forceinline__ uint32_t pack_h2(float lo, float hi) {
    uint32_t r;
    asm("cvt.rn.f16x2.f32 %0, %1, %2;" : "=r"(r) : "f"(hi), "f"(lo));
    return r;
}

__device__ __forceinline__ void mma16816(float* d,
                                         uint32_t a0, uint32_t a1, uint32_t a2, uint32_t a3,
                                         uint32_t b0, uint32_t b1) {
    asm volatile(
        "mma.sync.aligned.m16n8k16.row.col.f32.f16.f16.f32 "
        "{%0,%1,%2,%3}, {%4,%5,%6,%7}, {%8,%9}, {%0,%1,%2,%3};"
        : "+f"(d[0]), "+f"(d[1]), "+f"(d[2]), "+f"(d[3])
        : "r"(a0), "r"(a1), "r"(a2), "r"(a3), "r"(b0), "r"(b1));
}

#define CP16(dst, src) \
    asm volatile("cp.async.cg.shared.global [%0], [%1], 16;" :: "r"(dst), "l"(src) : "memory")
#define CP_COMMIT() asm volatile("cp.async.commit_group;" ::: "memory")
#define CP_WAIT1()  asm volatile("cp.async.wait_group 1;" ::: "memory")
#define CP_WAIT2()  asm volatile("cp.async.wait_group 2;" ::: "memory")

// ---------------- convert body: 1 thread -> 1 uint4 (4 output words) ----------
__device__ __forceinline__ void convert_blocks(const float* __restrict__ src,
                                               uint32_t* __restrict__ dst,
                                               int bc) {
    size_t n   = (size_t)bc * 256 + threadIdx.x;
    size_t kbi = n >> 2;
    int    w   = (int)(n & 3);
    const float2* s = (const float2*)src + kbi * 16 + w;
    uint32_t o[4];
#pragma unroll
    for (int i = 0; i < 4; ++i) {
        float2 f = s[4 * i];
        o[i] = pack_h2(f.x, f.y);
    }
    ((uint4*)dst)[kbi * 4 + w] = make_uint4(o[0], o[1], o[2], o[3]);
}

// ---------------- fused prep: hterm + convert W + convert x ------------------
__global__ __launch_bounds__(256)
void prep_kernel(const float* __restrict__ x,
                 const float* __restrict__ hx,
                 const float* __restrict__ Wih,
                 const float* __restrict__ Whh,
                 const float* __restrict__ bih,
                 const float* __restrict__ bhh) {
    int b = blockIdx.x;
    if (b < HTERM_BLOCKS) {
        int wid  = threadIdx.x >> 5;
        int lane = threadIdx.x & 31;
        int h = b * 8 + wid;

        float acc[B_DIM];
#pragma unroll
        for (int bb = 0; bb < B_DIM; ++bb) acc[bb] = 0.0f;

        const float4* wr = (const float4*)(Whh + (size_t)h * H_DIM);
#pragma unroll
        for (int it = 0; it < H_DIM / 128; ++it) {
            int j = lane + it * 32;
            float4 w4 = wr[j];
#pragma unroll
            for (int bb = 0; bb < B_DIM; ++bb) {
                float4 hv = ((const float4*)(hx + (size_t)bb * H_DIM))[j];
                acc[bb] += w4.x * hv.x + w4.y * hv.y + w4.z * hv.z + w4.w * hv.w;
            }
        }
#pragma unroll
        for (int bb = 0; bb < B_DIM; ++bb)
#pragma unroll
            for (int o = 16; o > 0; o >>= 1)
                acc[bb] += __shfl_xor_sync(0xFFFFFFFFu, acc[bb], o);

        if (lane == 0) {
            float bias = bih[h] + bhh[h];
#pragma unroll
            for (int bb = 0; bb < B_DIM; ++bb)
                g_hterm[bb * H_DIM + h] = acc[bb] + bias;
        }
    } else if (b < HTERM_BLOCKS + WCONV_BLOCKS) {
        convert_blocks(Wih, g_wh, b - HTERM_BLOCKS);
    } else {
        convert_blocks(x, g_xh, b - HTERM_BLOCKS - WCONV_BLOCKS);
    }
}

// ---------------- main GEMM + tanh ----------------
// 256 threads, 8 warps in 4(M)x2(N) grid, warp tile 32x64.
// Fragment addressing fully immediate-folded: one lane-constant A pointer and
// B pointer; stage (j*STAGE_U32) and row (nt*128, +128/256/384) offsets are
// unroll-time constants folded into the LDS immediate. Zero per-body addr ALU.
__global__ __launch_bounds__(THREADS, 2)
void gemm_tanh_kernel(float* __restrict__ out) {
    extern __shared__ __align__(16) uint32_t sbuf[];   // 64 KB, 4 stages

    int tid  = threadIdx.x;
    int wid  = tid >> 5;
    int lane = tid & 31;
    int g    = lane >> 2;
    int tg   = lane & 3;

    int mb = blockIdx.x >> 3;
    int nb = blockIdx.x & 7;           // 8 consecutive CTAs share x M-tile in L2
    int m0 = mb * BM;
    int n0 = nb * BN;
    int bb = m0 >> 11;

    int warp_m = (wid & 3) * 32;
    int warp_n = (wid >> 2) * 64;

    uint32_t sb = smem_u32(sbuf);

    // lane-constant fragment base pointers (stage 0)
    const uint32_t* aPtr = sbuf + (warp_m + g) * 16 + 4 * tg;
    const uint32_t* bPtr = sbuf + 2048 + (warp_n + g) * 16 + 4 * tg;

    // producer: each thread copies 4x16B per tile (A rows cr, cr+64; B rows cr, cr+64)
    int cr  = tid >> 2;
    int cch = (tid & 3) * 4;
    const uint32_t* srcA0 = g_xh + (size_t)(m0 + cr) * 512 + cch;   // row stride 512 u32
    const uint32_t* srcA1 = srcA0 + (size_t)64 * 512;
    const uint32_t* srcB0 = g_wh + (size_t)(n0 + cr) * 512 + cch;
    const uint32_t* srcB1 = srcB0 + (size_t)64 * 512;
    uint32_t dstA0 = sb + (cr * 16 + cch) * 4;
    uint32_t dstA1 = dstA0 + 64 * 64;
    uint32_t dstB0 = dstA0 + 8192;
    uint32_t dstB1 = dstB0 + 64 * 64;

    // tile t -> stage t&3 (smem byte offset (t&3)*16384), src offset t*16 u32
#define COPY_TILE(t_imm, soff) do {                                   \
    CP16(dstA0 + (soff), srcA0 + (t_imm) * 16);                       \
    CP16(dstA1 + (soff), srcA1 + (t_imm) * 16);                       \
    CP16(dstB0 + (soff), srcB0 + (t_imm) * 16);                       \
    CP16(dstB1 + (soff), srcB1 + (t_imm) * 16);                       \
} while (0)

    COPY_TILE(0, 0);      CP_COMMIT();
    COPY_TILE(1, 16384);  CP_COMMIT();
    COPY_TILE(2, 32768);  CP_COMMIT();

    float acc[2][8][4];
#pragma unroll
    for (int mt = 0; mt < 2; ++mt)
#pragma unroll
        for (int nt = 0; nt < 8; ++nt)
#pragma unroll
            for (int r = 0; r < 4; ++r) acc[mt][nt][r] = 0.0f;

    // ---- prologue: preload body-0 fragments from stage 0 ----
    CP_WAIT2();            // group 0 complete
    __syncthreads();       // visibility of all threads' copies for stage 0

    uint4 aL0, aH0, aL1, aH1, bfrag;
    aL0 = *(const uint4*)(aPtr);
    aH0 = *(const uint4*)(aPtr + 128);
    aL1 = *(const uint4*)(aPtr + 256);
    aH1 = *(const uint4*)(aPtr + 384);
    bfrag = *(const uint4*)(bPtr);

    for (int itb = 0; itb < KIT / 4; ++itb) {
#pragma unroll
        for (int j = 0; j < 4; ++j) {            // stage == j (compile-time)
            // wait_group 1: stages j AND j+1 of this window are complete
            CP_WAIT1();
            __syncthreads();

            int it = itb * 4 + j;
            if (it + 3 < KIT)
                COPY_TILE(j + 3, ((j + 3) & 3) * 16384);
            CP_COMMIT();

            // compile-time stage offsets for this body
            const uint32_t* bp  = bPtr + j * STAGE_U32;              // B, stage j
            const uint32_t* apn = aPtr + ((j + 1) & 3) * STAGE_U32;  // A, stage j+1
            const uint32_t* bpn = bPtr + ((j + 1) & 3) * STAGE_U32;  // B, stage j+1

            // ---- B-streamed MMA: all LDS at [base + immediate] ----
            uint4 bcur = bfrag;
#pragma unroll
            for (int nt = 0; nt < 8; ++nt) {
                uint4 bnxt;
                if (nt < 7)
                    bnxt = *(const uint4*)(bp + (nt + 1) * 128);
                else
                    bnxt = *(const uint4*)(bpn);         // next body nt=0
                mma16816(acc[0][nt], aL0.x, aH0.x, aL0.y, aH0.y, bcur.x, bcur.y);
                mma16816(acc[0][nt], aL0.z, aH0.z, aL0.w, aH0.w, bcur.z, bcur.w);
                mma16816(acc[1][nt], aL1.x, aH1.x, aL1.y, aH1.y, bcur.x, bcur.y);
                mma16816(acc[1][nt], aL1.z, aH1.z, aL1.w, aH1.w, bcur.z, bcur.w);
                bcur = bnxt;
            }
            bfrag = bcur;

            // ---- preload next body's A fragments (stage j+1, known complete) ----
            aL0 = *(const uint4*)(apn);
            aH0 = *(const uint4*)(apn + 128);
            aL1 = *(const uint4*)(apn + 256);
            aH1 = *(const uint4*)(apn + 384);
        }
        // advance source pointers by 4 tiles (64 u32)
        srcA0 += 64; srcA1 += 64; srcB0 += 64; srcB1 += 64;
    }

    // ---- epilogue: +hterm, tanh, store ----
    const float* ht = g_hterm + bb * H_DIM + n0;
#pragma unroll
    for (int mt = 0; mt < 2; ++mt) {
        int r0 = m0 + warp_m + mt * 16 + g;
#pragma unroll
        for (int nt = 0; nt < 8; ++nt) {
            int nloc = warp_n + nt * 8 + tg * 2;
            float h0 = __ldg(ht + nloc), h1 = __ldg(ht + nloc + 1);
            float* a = acc[mt][nt];
            float2 v0, v1;
            v0.x = tanh_fast(a[0] + h0);
            v0.y = tanh_fast(a[1] + h1);
            v1.x = tanh_fast(a[2] + h0);
            v1.y = tanh_fast(a[3] + h1);
            *(float2*)(out + (size_t)r0 * H_DIM + n0 + nloc) = v0;
            *(float2*)(out + (size_t)(r0 + 8) * H_DIM + n0 + nloc) = v1;
        }
    }
}

// ---------------- launch ----------------
extern "C" void kernel_launch(void* const* d_in, const int* in_sizes, int n_in,
                              void* d_out, int out_size) {
    const float* x   = (const float*)d_in[0];
    const float* hx  = (const float*)d_in[1];
    const float* Wih = (const float*)d_in[2];
    const float* Whh = (const float*)d_in[3];
    const float* bih = (const float*)d_in[4];
    const float* bhh = (const float*)d_in[5];
    float* out = (float*)d_out;

    cudaFuncSetAttribute(gemm_tanh_kernel,
                         cudaFuncAttributeMaxDynamicSharedMemorySize, SMEM_BYTES);

    prep_kernel<<<PREP_BLOCKS, 256>>>(x, hx, Wih, Whh, bih, bhh);
    gemm_tanh_kernel<<<(M_TOTAL / BM) * (H_DIM / BN), THREADS, SMEM_BYTES>>>(out);
}